// round 5
// baseline (speedup 1.0000x reference)
#include <cuda_runtime.h>
#include <math.h>
#include <stdint.h>

#define T_     256
#define B_     128
#define F_     1024
#define U_     512
#define G_     2048   // 4*U
#define CODES_ 1024
#define NBLK   128
#define UB     4
#define CHUNK  64

// Scratch (module-scope device allocations, permitted)
__device__ float g_xz[(size_t)T_ * G_ * B_];     // [t][c][b]  c = gate*512+u
__device__ float g_hseq[(size_t)T_ * U_ * B_];   // [t][u][b]
__device__ float g_h0[U_ * B_];
__device__ unsigned g_bar;

// ---------------------------------------------------------------------------
// helpers
// ---------------------------------------------------------------------------
__device__ __forceinline__ uint64_t splat2(float x) {
    uint64_t d; asm("mov.b64 %0, {%1, %1};" : "=l"(d) : "f"(x)); return d;
}
__device__ __forceinline__ void ffma2(uint64_t& d, uint64_t a, uint64_t b) {
    asm("fma.rn.f32x2 %0, %1, %2, %0;" : "+l"(d) : "l"(a), "l"(b));
}
__device__ __forceinline__ float2 unpack2(uint64_t d) {
    float2 r; asm("mov.b64 {%0, %1}, %2;" : "=f"(r.x), "=f"(r.y) : "l"(d)); return r;
}
__device__ __forceinline__ uint32_t f2t(float x) {
    uint32_t r; asm("cvt.rna.tf32.f32 %0, %1;" : "=r"(r) : "f"(x)); return r;
}
__device__ __forceinline__ void split4(float4 v, uint4& hi, uint4& lo) {
    hi.x = f2t(v.x); hi.y = f2t(v.y); hi.z = f2t(v.z); hi.w = f2t(v.w);
    lo.x = f2t(v.x - __uint_as_float(hi.x));
    lo.y = f2t(v.y - __uint_as_float(hi.y));
    lo.z = f2t(v.z - __uint_as_float(hi.z));
    lo.w = f2t(v.w - __uint_as_float(hi.w));
}
__device__ __forceinline__ void mma_tf32(float* d,
                                         const uint32_t* a, const uint32_t* b) {
    asm volatile("mma.sync.aligned.m16n8k8.row.col.f32.tf32.tf32.f32 "
        "{%0,%1,%2,%3}, {%4,%5,%6,%7}, {%8,%9}, {%0,%1,%2,%3};"
        : "+f"(d[0]), "+f"(d[1]), "+f"(d[2]), "+f"(d[3])
        : "r"(a[0]), "r"(a[1]), "r"(a[2]), "r"(a[3]), "r"(b[0]), "r"(b[1]));
}

// ---------------------------------------------------------------------------
__global__ void init_kernel() {
    int i = blockIdx.x * blockDim.x + threadIdx.x;
    if (i < U_ * B_) g_h0[i] = 0.f;
    if (i == 0) g_bar = 0u;
}

// ---------------------------------------------------------------------------
// GEMM 1 (tensor core, 3xTF32, double-buffered): xz = x @ W_in + b
// output transposed: g_xz[t][col][b]
// ---------------------------------------------------------------------------
#define AS_STRIDE 36
#define BS_STRIDE 136
#define XZ_STAGE  (2 * 128 * AS_STRIDE + 2 * 32 * BS_STRIDE)   // u32 per stage
#define DN_STAGE  (4 * 32 * BS_STRIDE)

__global__ __launch_bounds__(512)
void gemm_xz_tc(const float* __restrict__ A,
                const float* __restrict__ Bm,
                const float* __restrict__ bias)
{
    extern __shared__ uint32_t smx[];

    const int tid  = threadIdx.x;
    const int lane = tid & 31, w = tid >> 5;
    const int gid  = lane >> 2, tig = lane & 3;
    const int wm   = (w >> 2) * 32, wn = (w & 3) * 32;
    const int t    = blockIdx.y;
    const int row0 = t * 128;
    const int col0 = blockIdx.x * 128;

    // per-thread load coords
    const int arow0 = tid >> 3,        ak4 = (tid & 7) << 2;           // A r=0
    const int arow1 = (tid + 512) >> 3;                                 // A r=1
    const int bkk0 = tid >> 5,         bn4 = (tid & 31) << 2;          // B r=0
    const int bkk1 = (tid + 512) >> 5;                                  // B r=1

    float C[2][4][4];
#pragma unroll
    for (int im = 0; im < 2; im++)
#pragma unroll
        for (int in = 0; in < 4; in++)
#pragma unroll
            for (int r = 0; r < 4; r++) C[im][in][r] = 0.f;

    float4 pa0, pa1, pb0, pb1;
    // prologue: load k0 = 0
    pa0 = *reinterpret_cast<const float4*>(&A[(size_t)(row0 + arow0) * F_ + ak4]);
    pa1 = *reinterpret_cast<const float4*>(&A[(size_t)(row0 + arow1) * F_ + ak4]);
    pb0 = *reinterpret_cast<const float4*>(&Bm[(size_t)bkk0 * G_ + col0 + bn4]);
    pb1 = *reinterpret_cast<const float4*>(&Bm[(size_t)bkk1 * G_ + col0 + bn4]);
    {
        uint32_t* AsH = smx;
        uint32_t* AsL = AsH + 128 * AS_STRIDE;
        uint32_t* BsH = AsL + 128 * AS_STRIDE;
        uint32_t* BsL = BsH + 32 * BS_STRIDE;
        uint4 hi, lo;
        split4(pa0, hi, lo);
        *reinterpret_cast<uint4*>(&AsH[arow0 * AS_STRIDE + ak4]) = hi;
        *reinterpret_cast<uint4*>(&AsL[arow0 * AS_STRIDE + ak4]) = lo;
        split4(pa1, hi, lo);
        *reinterpret_cast<uint4*>(&AsH[arow1 * AS_STRIDE + ak4]) = hi;
        *reinterpret_cast<uint4*>(&AsL[arow1 * AS_STRIDE + ak4]) = lo;
        split4(pb0, hi, lo);
        *reinterpret_cast<uint4*>(&BsH[bkk0 * BS_STRIDE + bn4]) = hi;
        *reinterpret_cast<uint4*>(&BsL[bkk0 * BS_STRIDE + bn4]) = lo;
        split4(pb1, hi, lo);
        *reinterpret_cast<uint4*>(&BsH[bkk1 * BS_STRIDE + bn4]) = hi;
        *reinterpret_cast<uint4*>(&BsL[bkk1 * BS_STRIDE + bn4]) = lo;
    }
    __syncthreads();

    for (int k0 = 0; k0 < F_; k0 += 32) {
        const int s = (k0 >> 5) & 1;
        uint32_t* AsH = smx + s * XZ_STAGE;
        uint32_t* AsL = AsH + 128 * AS_STRIDE;
        uint32_t* BsH = AsL + 128 * AS_STRIDE;
        uint32_t* BsL = BsH + 32 * BS_STRIDE;
        const bool more = (k0 + 32 < F_);

        if (more) {   // prefetch next k-block into registers (overlaps MMAs)
            pa0 = *reinterpret_cast<const float4*>(
                &A[(size_t)(row0 + arow0) * F_ + k0 + 32 + ak4]);
            pa1 = *reinterpret_cast<const float4*>(
                &A[(size_t)(row0 + arow1) * F_ + k0 + 32 + ak4]);
            pb0 = *reinterpret_cast<const float4*>(
                &Bm[(size_t)(k0 + 32 + bkk0) * G_ + col0 + bn4]);
            pb1 = *reinterpret_cast<const float4*>(
                &Bm[(size_t)(k0 + 32 + bkk1) * G_ + col0 + bn4]);
        }

#pragma unroll
        for (int k8 = 0; k8 < 4; k8++) {
            uint32_t aH[2][4], aL[2][4], bH[4][2], bL[4][2];
#pragma unroll
            for (int im = 0; im < 2; im++) {
                int m = wm + im * 16;
                int p0 = (m + gid) * AS_STRIDE + k8 * 8 + tig;
                int p1 = (m + gid + 8) * AS_STRIDE + k8 * 8 + tig;
                aH[im][0] = AsH[p0];     aH[im][1] = AsH[p1];
                aH[im][2] = AsH[p0 + 4]; aH[im][3] = AsH[p1 + 4];
                aL[im][0] = AsL[p0];     aL[im][1] = AsL[p1];
                aL[im][2] = AsL[p0 + 4]; aL[im][3] = AsL[p1 + 4];
            }
#pragma unroll
            for (int in = 0; in < 4; in++) {
                int n = wn + in * 8 + gid;
                int kb = k8 * 8 + tig;
                bH[in][0] = BsH[kb * BS_STRIDE + n];
                bH[in][1] = BsH[(kb + 4) * BS_STRIDE + n];
                bL[in][0] = BsL[kb * BS_STRIDE + n];
                bL[in][1] = BsL[(kb + 4) * BS_STRIDE + n];
            }
#pragma unroll
            for (int im = 0; im < 2; im++)
#pragma unroll
                for (int in = 0; in < 4; in++) {
                    mma_tf32(C[im][in], aH[im], bH[in]);
                    mma_tf32(C[im][in], aL[im], bH[in]);
                    mma_tf32(C[im][in], aH[im], bL[in]);
                }
        }

        if (more) {   // split+store prefetched data into the other stage
            uint32_t* nAsH = smx + (s ^ 1) * XZ_STAGE;
            uint32_t* nAsL = nAsH + 128 * AS_STRIDE;
            uint32_t* nBsH = nAsL + 128 * AS_STRIDE;
            uint32_t* nBsL = nBsH + 32 * BS_STRIDE;
            uint4 hi, lo;
            split4(pa0, hi, lo);
            *reinterpret_cast<uint4*>(&nAsH[arow0 * AS_STRIDE + ak4]) = hi;
            *reinterpret_cast<uint4*>(&nAsL[arow0 * AS_STRIDE + ak4]) = lo;
            split4(pa1, hi, lo);
            *reinterpret_cast<uint4*>(&nAsH[arow1 * AS_STRIDE + ak4]) = hi;
            *reinterpret_cast<uint4*>(&nAsL[arow1 * AS_STRIDE + ak4]) = lo;
            split4(pb0, hi, lo);
            *reinterpret_cast<uint4*>(&nBsH[bkk0 * BS_STRIDE + bn4]) = hi;
            *reinterpret_cast<uint4*>(&nBsL[bkk0 * BS_STRIDE + bn4]) = lo;
            split4(pb1, hi, lo);
            *reinterpret_cast<uint4*>(&nBsH[bkk1 * BS_STRIDE + bn4]) = hi;
            *reinterpret_cast<uint4*>(&nBsL[bkk1 * BS_STRIDE + bn4]) = lo;
            __syncthreads();
        }
    }

    // transposed epilogue: g_xz[t][n][b]
#pragma unroll
    for (int im = 0; im < 2; im++) {
        int b = wm + im * 16 + gid;
#pragma unroll
        for (int in = 0; in < 4; in++) {
            int n = col0 + wn + in * 8 + 2 * tig;
            float bz0 = bias[n], bz1 = bias[n + 1];
            size_t p = ((size_t)t * G_ + n) * B_;
            g_xz[p + b]           = C[im][in][0] + bz0;
            g_xz[p + B_ + b]      = C[im][in][1] + bz1;
            g_xz[p + b + 8]       = C[im][in][2] + bz0;
            g_xz[p + B_ + b + 8]  = C[im][in][3] + bz1;
        }
    }
}

// ---------------------------------------------------------------------------
// GEMM 3 (tensor core, 3xTF32, double-buffered):
// out = relu(mask * (h @ W_dense) + b_dense), A from g_hseq [t][u][b]
// ---------------------------------------------------------------------------
__global__ __launch_bounds__(512)
void gemm_dense_tc(const float* __restrict__ Bm,
                   const float* __restrict__ bias,
                   const float* __restrict__ mask,
                   float* __restrict__ Cout)
{
    extern __shared__ uint32_t smx[];

    const int tid  = threadIdx.x;
    const int lane = tid & 31, w = tid >> 5;
    const int gid  = lane >> 2, tig = lane & 3;
    const int wm   = (w >> 2) * 32, wn = (w & 3) * 32;
    const int t    = blockIdx.y;
    const int col0 = blockIdx.x * 128;
    const float* Ablk = g_hseq + (size_t)t * U_ * B_;

    const int kk0 = tid >> 5, x4 = (tid & 31) << 2;
    const int kk1 = (tid + 512) >> 5;

    float C[2][4][4];
#pragma unroll
    for (int im = 0; im < 2; im++)
#pragma unroll
        for (int in = 0; in < 4; in++)
#pragma unroll
            for (int r = 0; r < 4; r++) C[im][in][r] = 0.f;

    float4 pa0, pa1, pb0, pb1;
    pa0 = *reinterpret_cast<const float4*>(&Ablk[(size_t)kk0 * B_ + x4]);
    pa1 = *reinterpret_cast<const float4*>(&Ablk[(size_t)kk1 * B_ + x4]);
    pb0 = *reinterpret_cast<const float4*>(&Bm[(size_t)kk0 * CODES_ + col0 + x4]);
    pb1 = *reinterpret_cast<const float4*>(&Bm[(size_t)kk1 * CODES_ + col0 + x4]);
    {
        uint32_t* AsH = smx;
        uint32_t* AsL = AsH + 32 * BS_STRIDE;
        uint32_t* BsH = AsL + 32 * BS_STRIDE;
        uint32_t* BsL = BsH + 32 * BS_STRIDE;
        uint4 hi, lo;
        split4(pa0, hi, lo);
        *reinterpret_cast<uint4*>(&AsH[kk0 * BS_STRIDE + x4]) = hi;
        *reinterpret_cast<uint4*>(&AsL[kk0 * BS_STRIDE + x4]) = lo;
        split4(pa1, hi, lo);
        *reinterpret_cast<uint4*>(&AsH[kk1 * BS_STRIDE + x4]) = hi;
        *reinterpret_cast<uint4*>(&AsL[kk1 * BS_STRIDE + x4]) = lo;
        split4(pb0, hi, lo);
        *reinterpret_cast<uint4*>(&BsH[kk0 * BS_STRIDE + x4]) = hi;
        *reinterpret_cast<uint4*>(&BsL[kk0 * BS_STRIDE + x4]) = lo;
        split4(pb1, hi, lo);
        *reinterpret_cast<uint4*>(&BsH[kk1 * BS_STRIDE + x4]) = hi;
        *reinterpret_cast<uint4*>(&BsL[kk1 * BS_STRIDE + x4]) = lo;
    }
    __syncthreads();

    for (int k0 = 0; k0 < U_; k0 += 32) {
        const int s = (k0 >> 5) & 1;
        uint32_t* AsH = smx + s * DN_STAGE;
        uint32_t* AsL = AsH + 32 * BS_STRIDE;
        uint32_t* BsH = AsL + 32 * BS_STRIDE;
        uint32_t* BsL = BsH + 32 * BS_STRIDE;
        const bool more = (k0 + 32 < U_);

        if (more) {
            pa0 = *reinterpret_cast<const float4*>(
                &Ablk[(size_t)(k0 + 32 + kk0) * B_ + x4]);
            pa1 = *reinterpret_cast<const float4*>(
                &Ablk[(size_t)(k0 + 32 + kk1) * B_ + x4]);
            pb0 = *reinterpret_cast<const float4*>(
                &Bm[(size_t)(k0 + 32 + kk0) * CODES_ + col0 + x4]);
            pb1 = *reinterpret_cast<const float4*>(
                &Bm[(size_t)(k0 + 32 + kk1) * CODES_ + col0 + x4]);
        }

#pragma unroll
        for (int k8 = 0; k8 < 4; k8++) {
            uint32_t aH[2][4], aL[2][4], bH[4][2], bL[4][2];
#pragma unroll
            for (int im = 0; im < 2; im++) {
                int m = wm + im * 16 + gid;
                int kb = k8 * 8 + tig;
                int p0 = kb * BS_STRIDE + m;
                aH[im][0] = AsH[p0];      aH[im][1] = AsH[p0 + 8];
                aH[im][2] = AsH[p0 + 4 * BS_STRIDE];
                aH[im][3] = AsH[p0 + 4 * BS_STRIDE + 8];
                aL[im][0] = AsL[p0];      aL[im][1] = AsL[p0 + 8];
                aL[im][2] = AsL[p0 + 4 * BS_STRIDE];
                aL[im][3] = AsL[p0 + 4 * BS_STRIDE + 8];
            }
#pragma unroll
            for (int in = 0; in < 4; in++) {
                int n = wn + in * 8 + gid;
                int kb = k8 * 8 + tig;
                bH[in][0] = BsH[kb * BS_STRIDE + n];
                bH[in][1] = BsH[(kb + 4) * BS_STRIDE + n];
                bL[in][0] = BsL[kb * BS_STRIDE + n];
                bL[in][1] = BsL[(kb + 4) * BS_STRIDE + n];
            }
#pragma unroll
            for (int im = 0; im < 2; im++)
#pragma unroll
                for (int in = 0; in < 4; in++) {
                    mma_tf32(C[im][in], aH[im], bH[in]);
                    mma_tf32(C[im][in], aL[im], bH[in]);
                    mma_tf32(C[im][in], aH[im], bL[in]);
                }
        }

        if (more) {
            uint32_t* nAsH = smx + (s ^ 1) * DN_STAGE;
            uint32_t* nAsL = nAsH + 32 * BS_STRIDE;
            uint32_t* nBsH = nAsL + 32 * BS_STRIDE;
            uint32_t* nBsL = nBsH + 32 * BS_STRIDE;
            uint4 hi, lo;
            split4(pa0, hi, lo);
            *reinterpret_cast<uint4*>(&nAsH[kk0 * BS_STRIDE + x4]) = hi;
            *reinterpret_cast<uint4*>(&nAsL[kk0 * BS_STRIDE + x4]) = lo;
            split4(pa1, hi, lo);
            *reinterpret_cast<uint4*>(&nAsH[kk1 * BS_STRIDE + x4]) = hi;
            *reinterpret_cast<uint4*>(&nAsL[kk1 * BS_STRIDE + x4]) = lo;
            split4(pb0, hi, lo);
            *reinterpret_cast<uint4*>(&nBsH[kk0 * BS_STRIDE + x4]) = hi;
            *reinterpret_cast<uint4*>(&nBsL[kk0 * BS_STRIDE + x4]) = lo;
            split4(pb1, hi, lo);
            *reinterpret_cast<uint4*>(&nBsH[kk1 * BS_STRIDE + x4]) = hi;
            *reinterpret_cast<uint4*>(&nBsL[kk1 * BS_STRIDE + x4]) = lo;
            __syncthreads();
        }
    }

#pragma unroll
    for (int im = 0; im < 2; im++) {
        int b = wm + im * 16 + gid;
        int r0 = t * 128 + b, r1 = r0 + 8;
        float m0 = mask[r0], m1 = mask[r1];
#pragma unroll
        for (int in = 0; in < 4; in++) {
            int n = col0 + wn + in * 8 + 2 * tig;
            float bz0 = bias[n], bz1 = bias[n + 1];
            Cout[(size_t)r0 * CODES_ + n]     = fmaxf(C[im][in][0] * m0 + bz0, 0.f);
            Cout[(size_t)r0 * CODES_ + n + 1] = fmaxf(C[im][in][1] * m0 + bz1, 0.f);
            Cout[(size_t)r1 * CODES_ + n]     = fmaxf(C[im][in][2] * m1 + bz0, 0.f);
            Cout[(size_t)r1 * CODES_ + n + 1] = fmaxf(C[im][in][3] * m1 + bz1, 0.f);
        }
    }
}

// ---------------------------------------------------------------------------
// Persistent LSTM: W pre-splatted into u64 SMEM -> 6-instr inner loop
// smem: Ws2 u64[512*16] (64KB) | buf f32[2*CHUNK*128] (64KB) | cs f32[512]
// ---------------------------------------------------------------------------
__global__ __launch_bounds__(256)
void lstm_persistent_kernel(const float* __restrict__ W_rec)
{
    extern __shared__ float sm[];
    uint64_t* Ws2 = reinterpret_cast<uint64_t*>(sm);        // 512*16 u64
    float* buf = sm + 512 * 32;                             // 2*CHUNK*128
    float* cs  = buf + 2 * CHUNK * 128;                     // 512

    const int tid  = threadIdx.x;
    const int ublk = blockIdx.x * UB;

    // pre-splat W slice: Ws2[k*16 + c] = splat(W_rec[k][gate(c)*U + ublk + ul(c)])
    for (int idx = tid; idx < 512 * 16; idx += 256) {
        int k = idx >> 4, c = idx & 15;
        float wv = W_rec[(size_t)k * G_ + (c >> 2) * U_ + ublk + (c & 3)];
        Ws2[idx] = splat2(wv);
    }
    for (int idx = tid; idx < 4 * 128; idx += 256) cs[idx] = 0.f;
    __syncthreads();

    const int cq = tid & 7;                // col-pair index (c0 = 2*cq)
    const int c0 = cq * 2;
    const int b0 = (tid >> 3) * 4;

    for (int t = 0; t < T_; t++) {
        const float* hp = (t == 0) ? g_h0 : (g_hseq + (size_t)(t - 1) * U_ * B_);

        uint64_t acc[2][2];
        acc[0][0] = acc[0][1] = acc[1][0] = acc[1][1] = 0ull;

        float4 pf[8];
#pragma unroll
        for (int i = 0; i < 8; i++)
            pf[i] = *reinterpret_cast<const float4*>(&hp[(size_t)(i * 256 + tid) * 4]);

        for (int kc = 0; kc < U_ / CHUNK; kc++) {
            float* bc = buf + (kc & 1) * (CHUNK * 128);
#pragma unroll
            for (int i = 0; i < 8; i++)
                *reinterpret_cast<float4*>(&bc[(i * 256 + tid) * 4]) = pf[i];
            __syncthreads();
            if (kc + 1 < U_ / CHUNK) {
                const float* hq = hp + (size_t)(kc + 1) * CHUNK * 128;
#pragma unroll
                for (int i = 0; i < 8; i++)
                    pf[i] = *reinterpret_cast<const float4*>(&hq[(size_t)(i * 256 + tid) * 4]);
            }
            const uint64_t* wk = Ws2 + (size_t)kc * CHUNK * 16 + c0;
#pragma unroll
            for (int kk = 0; kk < CHUNK; kk++) {
                ulonglong2 h = *reinterpret_cast<ulonglong2*>(&bc[kk * 128 + b0]);
                ulonglong2 wv = *reinterpret_cast<const ulonglong2*>(&wk[kk * 16]);
                ffma2(acc[0][0], h.x, wv.x);
                ffma2(acc[1][0], h.y, wv.x);
                ffma2(acc[0][1], h.x, wv.y);
                ffma2(acc[1][1], h.y, wv.y);
            }
        }

        float* stash = buf;
#pragma unroll
        for (int c = 0; c < 2; c++) {
            float2 v0 = unpack2(acc[0][c]);
            float2 v1 = unpack2(acc[1][c]);
            *reinterpret_cast<float2*>(&stash[(c0 + c) * 128 + b0])     = v0;
            *reinterpret_cast<float2*>(&stash[(c0 + c) * 128 + b0 + 2]) = v1;
        }
        __syncthreads();

        const float* xz_t = g_xz + (size_t)t * G_ * B_;
        float* h_out = g_hseq + (size_t)t * U_ * B_;
#pragma unroll
        for (int r = 0; r < 2; r++) {
            int p = tid + r * 256;
            int b = p & 127, ul = p >> 7;
            int u = ublk + ul;
            float zi = stash[(0 * 4 + ul) * 128 + b] + xz_t[(size_t)(0 * U_ + u) * B_ + b];
            float zf = stash[(1 * 4 + ul) * 128 + b] + xz_t[(size_t)(1 * U_ + u) * B_ + b];
            float zg = stash[(2 * 4 + ul) * 128 + b] + xz_t[(size_t)(2 * U_ + u) * B_ + b];
            float zo = stash[(3 * 4 + ul) * 128 + b] + xz_t[(size_t)(3 * U_ + u) * B_ + b];
            float ig = 1.f / (1.f + __expf(-zi));
            float fg = 1.f / (1.f + __expf(-zf));
            float gg = 1.f - 2.f / (1.f + __expf(2.f * zg));
            float og = 1.f / (1.f + __expf(-zo));
            float cn = fg * cs[ul * 128 + b] + ig * gg;
            cs[ul * 128 + b] = cn;
            float th = 1.f - 2.f / (1.f + __expf(2.f * cn));
            h_out[(size_t)u * B_ + b] = og * th;
        }

        __threadfence();
        __syncthreads();
        if (tid == 0) {
            atomicAdd(&g_bar, 1u);
            unsigned tgt = (unsigned)(NBLK * (t + 1));
            while (*((volatile unsigned*)&g_bar) < tgt) { }
            __threadfence();
        }
        __syncthreads();
    }
}

// ---------------------------------------------------------------------------
__global__ __launch_bounds__(256)
void softmax_kernel(float* __restrict__ out)
{
    __shared__ float red[256];
    const int row = blockIdx.x;
    const int tid = threadIdx.x;
    float* p = out + (size_t)row * CODES_;

    float v[4];
    float m = -1e30f;
#pragma unroll
    for (int i = 0; i < 4; i++) {
        v[i] = p[tid + i * 256];
        m = fmaxf(m, v[i]);
    }
    red[tid] = m;
    __syncthreads();
    for (int s = 128; s > 0; s >>= 1) {
        if (tid < s) red[tid] = fmaxf(red[tid], red[tid + s]);
        __syncthreads();
    }
    m = red[0];
    __syncthreads();

    float sum = 0.f;
#pragma unroll
    for (int i = 0; i < 4; i++) {
        v[i] = __expf(v[i] - m);
        sum += v[i];
    }
    red[tid] = sum;
    __syncthreads();
    for (int s = 128; s > 0; s >>= 1) {
        if (tid < s) red[tid] += red[tid + s];
        __syncthreads();
    }
    float inv = 1.f / red[0];
#pragma unroll
    for (int i = 0; i < 4; i++) p[tid + i * 256] = v[i] * inv;
}

// ---------------------------------------------------------------------------
extern "C" void kernel_launch(void* const* d_in, const int* in_sizes, int n_in,
                              void* d_out, int out_size)
{
    const float* x       = (const float*)d_in[0];
    const float* mask    = (const float*)d_in[1];
    const float* W_in    = (const float*)d_in[2];
    const float* W_rec   = (const float*)d_in[3];
    const float* b_lstm  = (const float*)d_in[4];
    const float* W_dense = (const float*)d_in[5];
    const float* b_dense = (const float*)d_in[6];
    float* out = (float*)d_out;

    const int smem_xz    = 2 * XZ_STAGE * 4;
    const int smem_dense = 2 * DN_STAGE * 4;
    const int smem_lstm  = (512 * 32 + 2 * CHUNK * 128 + 4 * 128) * (int)sizeof(float);
    static int attr_set = 0;
    if (!attr_set) {
        cudaFuncSetAttribute(gemm_xz_tc,
                             cudaFuncAttributeMaxDynamicSharedMemorySize, smem_xz);
        cudaFuncSetAttribute(gemm_dense_tc,
                             cudaFuncAttributeMaxDynamicSharedMemorySize, smem_dense);
        cudaFuncSetAttribute(lstm_persistent_kernel,
                             cudaFuncAttributeMaxDynamicSharedMemorySize, smem_lstm);
        attr_set = 1;
    }

    init_kernel<<<(U_ * B_ + 255) / 256, 256>>>();

    {   // xz = x @ W_in + b  (TC 3xTF32, double-buffered, transposed output)
        dim3 grid(G_ / 128, T_);
        gemm_xz_tc<<<grid, 512, smem_xz>>>(x, W_in, b_lstm);
    }

    lstm_persistent_kernel<<<NBLK, 256, smem_lstm>>>(W_rec);

    {   // dense + mask + relu (TC 3xTF32, double-buffered)
        dim3 grid(CODES_ / 128, T_);
        gemm_dense_tc<<<grid, 512, smem_dense>>>(W_dense, b_dense, mask, out);
    }

    softmax_kernel<<<T_ * B_, 256>>>(out);
}

// round 6
// speedup vs baseline: 1.2882x; 1.2882x over previous
#include <cuda_runtime.h>
#include <math.h>
#include <stdint.h>

#define T_     256
#define B_     128
#define F_     1024
#define U_     512
#define G_     2048   // 4*U
#define CODES_ 1024
#define NBLK   128

// Scratch (module-scope device allocations, permitted)
__device__ float g_xz[(size_t)T_ * G_ * B_];     // [t][c][b]  c = gate*512+u
__device__ float g_hseq[(size_t)T_ * U_ * B_];   // [t][u][b]
__device__ float g_h0[U_ * B_];
__device__ unsigned g_bar;

// ---------------------------------------------------------------------------
// helpers
// ---------------------------------------------------------------------------
__device__ __forceinline__ uint64_t splat2(float x) {
    uint64_t d; asm("mov.b64 %0, {%1, %1};" : "=l"(d) : "f"(x)); return d;
}
__device__ __forceinline__ void ffma2(uint64_t& d, uint64_t a, uint64_t b) {
    asm("fma.rn.f32x2 %0, %1, %2, %0;" : "+l"(d) : "l"(a), "l"(b));
}
__device__ __forceinline__ float2 unpack2(uint64_t d) {
    float2 r; asm("mov.b64 {%0, %1}, %2;" : "=f"(r.x), "=f"(r.y) : "l"(d)); return r;
}
__device__ __forceinline__ uint32_t f2t(float x) {
    uint32_t r; asm("cvt.rna.tf32.f32 %0, %1;" : "=r"(r) : "f"(x)); return r;
}
__device__ __forceinline__ void split4(float4 v, uint4& hi, uint4& lo) {
    hi.x = f2t(v.x); hi.y = f2t(v.y); hi.z = f2t(v.z); hi.w = f2t(v.w);
    lo.x = f2t(v.x - __uint_as_float(hi.x));
    lo.y = f2t(v.y - __uint_as_float(hi.y));
    lo.z = f2t(v.z - __uint_as_float(hi.z));
    lo.w = f2t(v.w - __uint_as_float(hi.w));
}
__device__ __forceinline__ void mma_tf32(float* d,
                                         const uint32_t* a, const uint32_t* b) {
    asm volatile("mma.sync.aligned.m16n8k8.row.col.f32.tf32.tf32.f32 "
        "{%0,%1,%2,%3}, {%4,%5,%6,%7}, {%8,%9}, {%0,%1,%2,%3};"
        : "+f"(d[0]), "+f"(d[1]), "+f"(d[2]), "+f"(d[3])
        : "r"(a[0]), "r"(a[1]), "r"(a[2]), "r"(a[3]), "r"(b[0]), "r"(b[1]));
}

// ---------------------------------------------------------------------------
__global__ void init_kernel() {
    int i = blockIdx.x * blockDim.x + threadIdx.x;
    if (i < U_ * B_) g_h0[i] = 0.f;
    if (i == 0) g_bar = 0u;
}

// ---------------------------------------------------------------------------
// GEMM 1 (tensor core, 3xTF32, double-buffered): xz = x @ W_in + b
// output transposed: g_xz[t][col][b]
// ---------------------------------------------------------------------------
#define AS_STRIDE 36
#define BS_STRIDE 136
#define XZ_STAGE  (2 * 128 * AS_STRIDE + 2 * 32 * BS_STRIDE)   // u32 per stage
#define DN_STAGE  (4 * 32 * BS_STRIDE)

__global__ __launch_bounds__(512)
void gemm_xz_tc(const float* __restrict__ A,
                const float* __restrict__ Bm,
                const float* __restrict__ bias)
{
    extern __shared__ uint32_t smx[];

    const int tid  = threadIdx.x;
    const int lane = tid & 31, w = tid >> 5;
    const int gid  = lane >> 2, tig = lane & 3;
    const int wm   = (w >> 2) * 32, wn = (w & 3) * 32;
    const int t    = blockIdx.y;
    const int row0 = t * 128;
    const int col0 = blockIdx.x * 128;

    const int arow0 = tid >> 3,        ak4 = (tid & 7) << 2;
    const int arow1 = (tid + 512) >> 3;
    const int bkk0 = tid >> 5,         bn4 = (tid & 31) << 2;
    const int bkk1 = (tid + 512) >> 5;

    float C[2][4][4];
#pragma unroll
    for (int im = 0; im < 2; im++)
#pragma unroll
        for (int in = 0; in < 4; in++)
#pragma unroll
            for (int r = 0; r < 4; r++) C[im][in][r] = 0.f;

    float4 pa0, pa1, pb0, pb1;
    pa0 = *reinterpret_cast<const float4*>(&A[(size_t)(row0 + arow0) * F_ + ak4]);
    pa1 = *reinterpret_cast<const float4*>(&A[(size_t)(row0 + arow1) * F_ + ak4]);
    pb0 = *reinterpret_cast<const float4*>(&Bm[(size_t)bkk0 * G_ + col0 + bn4]);
    pb1 = *reinterpret_cast<const float4*>(&Bm[(size_t)bkk1 * G_ + col0 + bn4]);
    {
        uint32_t* AsH = smx;
        uint32_t* AsL = AsH + 128 * AS_STRIDE;
        uint32_t* BsH = AsL + 128 * AS_STRIDE;
        uint32_t* BsL = BsH + 32 * BS_STRIDE;
        uint4 hi, lo;
        split4(pa0, hi, lo);
        *reinterpret_cast<uint4*>(&AsH[arow0 * AS_STRIDE + ak4]) = hi;
        *reinterpret_cast<uint4*>(&AsL[arow0 * AS_STRIDE + ak4]) = lo;
        split4(pa1, hi, lo);
        *reinterpret_cast<uint4*>(&AsH[arow1 * AS_STRIDE + ak4]) = hi;
        *reinterpret_cast<uint4*>(&AsL[arow1 * AS_STRIDE + ak4]) = lo;
        split4(pb0, hi, lo);
        *reinterpret_cast<uint4*>(&BsH[bkk0 * BS_STRIDE + bn4]) = hi;
        *reinterpret_cast<uint4*>(&BsL[bkk0 * BS_STRIDE + bn4]) = lo;
        split4(pb1, hi, lo);
        *reinterpret_cast<uint4*>(&BsH[bkk1 * BS_STRIDE + bn4]) = hi;
        *reinterpret_cast<uint4*>(&BsL[bkk1 * BS_STRIDE + bn4]) = lo;
    }
    __syncthreads();

    for (int k0 = 0; k0 < F_; k0 += 32) {
        const int s = (k0 >> 5) & 1;
        uint32_t* AsH = smx + s * XZ_STAGE;
        uint32_t* AsL = AsH + 128 * AS_STRIDE;
        uint32_t* BsH = AsL + 128 * AS_STRIDE;
        uint32_t* BsL = BsH + 32 * BS_STRIDE;
        const bool more = (k0 + 32 < F_);

        if (more) {
            pa0 = *reinterpret_cast<const float4*>(
                &A[(size_t)(row0 + arow0) * F_ + k0 + 32 + ak4]);
            pa1 = *reinterpret_cast<const float4*>(
                &A[(size_t)(row0 + arow1) * F_ + k0 + 32 + ak4]);
            pb0 = *reinterpret_cast<const float4*>(
                &Bm[(size_t)(k0 + 32 + bkk0) * G_ + col0 + bn4]);
            pb1 = *reinterpret_cast<const float4*>(
                &Bm[(size_t)(k0 + 32 + bkk1) * G_ + col0 + bn4]);
        }

#pragma unroll
        for (int k8 = 0; k8 < 4; k8++) {
            uint32_t aH[2][4], aL[2][4], bH[4][2], bL[4][2];
#pragma unroll
            for (int im = 0; im < 2; im++) {
                int m = wm + im * 16;
                int p0 = (m + gid) * AS_STRIDE + k8 * 8 + tig;
                int p1 = (m + gid + 8) * AS_STRIDE + k8 * 8 + tig;
                aH[im][0] = AsH[p0];     aH[im][1] = AsH[p1];
                aH[im][2] = AsH[p0 + 4]; aH[im][3] = AsH[p1 + 4];
                aL[im][0] = AsL[p0];     aL[im][1] = AsL[p1];
                aL[im][2] = AsL[p0 + 4]; aL[im][3] = AsL[p1 + 4];
            }
#pragma unroll
            for (int in = 0; in < 4; in++) {
                int n = wn + in * 8 + gid;
                int kb = k8 * 8 + tig;
                bH[in][0] = BsH[kb * BS_STRIDE + n];
                bH[in][1] = BsH[(kb + 4) * BS_STRIDE + n];
                bL[in][0] = BsL[kb * BS_STRIDE + n];
                bL[in][1] = BsL[(kb + 4) * BS_STRIDE + n];
            }
#pragma unroll
            for (int im = 0; im < 2; im++)
#pragma unroll
                for (int in = 0; in < 4; in++) {
                    mma_tf32(C[im][in], aH[im], bH[in]);
                    mma_tf32(C[im][in], aL[im], bH[in]);
                    mma_tf32(C[im][in], aH[im], bL[in]);
                }
        }

        if (more) {
            uint32_t* nAsH = smx + (s ^ 1) * XZ_STAGE;
            uint32_t* nAsL = nAsH + 128 * AS_STRIDE;
            uint32_t* nBsH = nAsL + 128 * AS_STRIDE;
            uint32_t* nBsL = nBsH + 32 * BS_STRIDE;
            uint4 hi, lo;
            split4(pa0, hi, lo);
            *reinterpret_cast<uint4*>(&nAsH[arow0 * AS_STRIDE + ak4]) = hi;
            *reinterpret_cast<uint4*>(&nAsL[arow0 * AS_STRIDE + ak4]) = lo;
            split4(pa1, hi, lo);
            *reinterpret_cast<uint4*>(&nAsH[arow1 * AS_STRIDE + ak4]) = hi;
            *reinterpret_cast<uint4*>(&nAsL[arow1 * AS_STRIDE + ak4]) = lo;
            split4(pb0, hi, lo);
            *reinterpret_cast<uint4*>(&nBsH[bkk0 * BS_STRIDE + bn4]) = hi;
            *reinterpret_cast<uint4*>(&nBsL[bkk0 * BS_STRIDE + bn4]) = lo;
            split4(pb1, hi, lo);
            *reinterpret_cast<uint4*>(&nBsH[bkk1 * BS_STRIDE + bn4]) = hi;
            *reinterpret_cast<uint4*>(&nBsL[bkk1 * BS_STRIDE + bn4]) = lo;
            __syncthreads();
        }
    }

#pragma unroll
    for (int im = 0; im < 2; im++) {
        int b = wm + im * 16 + gid;
#pragma unroll
        for (int in = 0; in < 4; in++) {
            int n = col0 + wn + in * 8 + 2 * tig;
            float bz0 = bias[n], bz1 = bias[n + 1];
            size_t p = ((size_t)t * G_ + n) * B_;
            g_xz[p + b]           = C[im][in][0] + bz0;
            g_xz[p + B_ + b]      = C[im][in][1] + bz1;
            g_xz[p + b + 8]       = C[im][in][2] + bz0;
            g_xz[p + B_ + b + 8]  = C[im][in][3] + bz1;
        }
    }
}

// ---------------------------------------------------------------------------
// GEMM 3 (tensor core, 3xTF32, double-buffered):
// out = relu(mask * (h @ W_dense) + b_dense), A from g_hseq [t][u][b]
// ---------------------------------------------------------------------------
__global__ __launch_bounds__(512)
void gemm_dense_tc(const float* __restrict__ Bm,
                   const float* __restrict__ bias,
                   const float* __restrict__ mask,
                   float* __restrict__ Cout)
{
    extern __shared__ uint32_t smx[];

    const int tid  = threadIdx.x;
    const int lane = tid & 31, w = tid >> 5;
    const int gid  = lane >> 2, tig = lane & 3;
    const int wm   = (w >> 2) * 32, wn = (w & 3) * 32;
    const int t    = blockIdx.y;
    const int col0 = blockIdx.x * 128;
    const float* Ablk = g_hseq + (size_t)t * U_ * B_;

    const int kk0 = tid >> 5, x4 = (tid & 31) << 2;
    const int kk1 = (tid + 512) >> 5;

    float C[2][4][4];
#pragma unroll
    for (int im = 0; im < 2; im++)
#pragma unroll
        for (int in = 0; in < 4; in++)
#pragma unroll
            for (int r = 0; r < 4; r++) C[im][in][r] = 0.f;

    float4 pa0, pa1, pb0, pb1;
    pa0 = *reinterpret_cast<const float4*>(&Ablk[(size_t)kk0 * B_ + x4]);
    pa1 = *reinterpret_cast<const float4*>(&Ablk[(size_t)kk1 * B_ + x4]);
    pb0 = *reinterpret_cast<const float4*>(&Bm[(size_t)kk0 * CODES_ + col0 + x4]);
    pb1 = *reinterpret_cast<const float4*>(&Bm[(size_t)kk1 * CODES_ + col0 + x4]);
    {
        uint32_t* AsH = smx;
        uint32_t* AsL = AsH + 32 * BS_STRIDE;
        uint32_t* BsH = AsL + 32 * BS_STRIDE;
        uint32_t* BsL = BsH + 32 * BS_STRIDE;
        uint4 hi, lo;
        split4(pa0, hi, lo);
        *reinterpret_cast<uint4*>(&AsH[kk0 * BS_STRIDE + x4]) = hi;
        *reinterpret_cast<uint4*>(&AsL[kk0 * BS_STRIDE + x4]) = lo;
        split4(pa1, hi, lo);
        *reinterpret_cast<uint4*>(&AsH[kk1 * BS_STRIDE + x4]) = hi;
        *reinterpret_cast<uint4*>(&AsL[kk1 * BS_STRIDE + x4]) = lo;
        split4(pb0, hi, lo);
        *reinterpret_cast<uint4*>(&BsH[kk0 * BS_STRIDE + x4]) = hi;
        *reinterpret_cast<uint4*>(&BsL[kk0 * BS_STRIDE + x4]) = lo;
        split4(pb1, hi, lo);
        *reinterpret_cast<uint4*>(&BsH[kk1 * BS_STRIDE + x4]) = hi;
        *reinterpret_cast<uint4*>(&BsL[kk1 * BS_STRIDE + x4]) = lo;
    }
    __syncthreads();

    for (int k0 = 0; k0 < U_; k0 += 32) {
        const int s = (k0 >> 5) & 1;
        uint32_t* AsH = smx + s * DN_STAGE;
        uint32_t* AsL = AsH + 32 * BS_STRIDE;
        uint32_t* BsH = AsL + 32 * BS_STRIDE;
        uint32_t* BsL = BsH + 32 * BS_STRIDE;
        const bool more = (k0 + 32 < U_);

        if (more) {
            pa0 = *reinterpret_cast<const float4*>(
                &Ablk[(size_t)(k0 + 32 + kk0) * B_ + x4]);
            pa1 = *reinterpret_cast<const float4*>(
                &Ablk[(size_t)(k0 + 32 + kk1) * B_ + x4]);
            pb0 = *reinterpret_cast<const float4*>(
                &Bm[(size_t)(k0 + 32 + kk0) * CODES_ + col0 + x4]);
            pb1 = *reinterpret_cast<const float4*>(
                &Bm[(size_t)(k0 + 32 + kk1) * CODES_ + col0 + x4]);
        }

#pragma unroll
        for (int k8 = 0; k8 < 4; k8++) {
            uint32_t aH[2][4], aL[2][4], bH[4][2], bL[4][2];
#pragma unroll
            for (int im = 0; im < 2; im++) {
                int m = wm + im * 16 + gid;
                int kb = k8 * 8 + tig;
                int p0 = kb * BS_STRIDE + m;
                aH[im][0] = AsH[p0];      aH[im][1] = AsH[p0 + 8];
                aH[im][2] = AsH[p0 + 4 * BS_STRIDE];
                aH[im][3] = AsH[p0 + 4 * BS_STRIDE + 8];
                aL[im][0] = AsL[p0];      aL[im][1] = AsL[p0 + 8];
                aL[im][2] = AsL[p0 + 4 * BS_STRIDE];
                aL[im][3] = AsL[p0 + 4 * BS_STRIDE + 8];
            }
#pragma unroll
            for (int in = 0; in < 4; in++) {
                int n = wn + in * 8 + gid;
                int kb = k8 * 8 + tig;
                bH[in][0] = BsH[kb * BS_STRIDE + n];
                bH[in][1] = BsH[(kb + 4) * BS_STRIDE + n];
                bL[in][0] = BsL[kb * BS_STRIDE + n];
                bL[in][1] = BsL[(kb + 4) * BS_STRIDE + n];
            }
#pragma unroll
            for (int im = 0; im < 2; im++)
#pragma unroll
                for (int in = 0; in < 4; in++) {
                    mma_tf32(C[im][in], aH[im], bH[in]);
                    mma_tf32(C[im][in], aL[im], bH[in]);
                    mma_tf32(C[im][in], aH[im], bL[in]);
                }
        }

        if (more) {
            uint32_t* nAsH = smx + (s ^ 1) * DN_STAGE;
            uint32_t* nAsL = nAsH + 32 * BS_STRIDE;
            uint32_t* nBsH = nAsL + 32 * BS_STRIDE;
            uint32_t* nBsL = nBsH + 32 * BS_STRIDE;
            uint4 hi, lo;
            split4(pa0, hi, lo);
            *reinterpret_cast<uint4*>(&nAsH[kk0 * BS_STRIDE + x4]) = hi;
            *reinterpret_cast<uint4*>(&nAsL[kk0 * BS_STRIDE + x4]) = lo;
            split4(pa1, hi, lo);
            *reinterpret_cast<uint4*>(&nAsH[kk1 * BS_STRIDE + x4]) = hi;
            *reinterpret_cast<uint4*>(&nAsL[kk1 * BS_STRIDE + x4]) = lo;
            split4(pb0, hi, lo);
            *reinterpret_cast<uint4*>(&nBsH[kk0 * BS_STRIDE + x4]) = hi;
            *reinterpret_cast<uint4*>(&nBsL[kk0 * BS_STRIDE + x4]) = lo;
            split4(pb1, hi, lo);
            *reinterpret_cast<uint4*>(&nBsH[kk1 * BS_STRIDE + x4]) = hi;
            *reinterpret_cast<uint4*>(&nBsL[kk1 * BS_STRIDE + x4]) = lo;
            __syncthreads();
        }
    }

#pragma unroll
    for (int im = 0; im < 2; im++) {
        int b = wm + im * 16 + gid;
        int r0 = t * 128 + b, r1 = r0 + 8;
        float m0 = mask[r0], m1 = mask[r1];
#pragma unroll
        for (int in = 0; in < 4; in++) {
            int n = col0 + wn + in * 8 + 2 * tig;
            float bz0 = bias[n], bz1 = bias[n + 1];
            Cout[(size_t)r0 * CODES_ + n]     = fmaxf(C[im][in][0] * m0 + bz0, 0.f);
            Cout[(size_t)r0 * CODES_ + n + 1] = fmaxf(C[im][in][1] * m0 + bz1, 0.f);
            Cout[(size_t)r1 * CODES_ + n]     = fmaxf(C[im][in][2] * m1 + bz0, 0.f);
            Cout[(size_t)r1 * CODES_ + n + 1] = fmaxf(C[im][in][3] * m1 + bz1, 0.f);
        }
    }
}

// ---------------------------------------------------------------------------
// Persistent LSTM, 2D partition: 32 unit-blocks x 4 batch-blocks.
// Block (ub, bb): units [ub*16, ub*16+16), batch [bb*32, bb*32+32).
// W slice 512x64 resident in SMEM (128KB); h staged 64KB/step in 4 chunks.
// smem: Ws f32[512*64] | buf f32[2*128*32] | cs f32[16*32]
// ---------------------------------------------------------------------------
__global__ __launch_bounds__(256)
void lstm_persistent_kernel(const float* __restrict__ W_rec)
{
    extern __shared__ float sm[];
    float* Ws  = sm;                    // [k][c], c = gate*16 + ulocal
    float* buf = sm + 512 * 64;         // 2 stages of [128][32]
    float* cs  = buf + 2 * 128 * 32;    // [ulocal][32]

    const int tid = threadIdx.x;
    const int ub  = blockIdx.x >> 2;    // 0..31
    const int bb  = blockIdx.x & 3;     // 0..3
    const int bg0 = bb * 32;

    // W slice: Ws[k*64 + c] = W_rec[k][ (c>>4)*U + ub*16 + (c&15) ]
    for (int idx = tid; idx < 512 * 64; idx += 256) {
        int k = idx >> 6, c = idx & 63;
        Ws[idx] = W_rec[(size_t)k * G_ + (c >> 4) * U_ + ub * 16 + (c & 15)];
    }
    for (int i = tid; i < 16 * 32; i += 256) cs[i] = 0.f;
    __syncthreads();

    const int c0 = (tid & 31) * 2;      // gate-col pair within 64
    const int b0 = (tid >> 5) * 4;      // batch quad within 32
    const int eul = tid >> 4;           // epilogue unit 0..15
    const int eb  = (tid * 2) & 31;     // epilogue batch pair base

    for (int t = 0; t < T_; t++) {
        const float* hp = (t == 0) ? g_h0 : (g_hseq + (size_t)(t - 1) * U_ * B_);
        const float* xz_t = g_xz + (size_t)t * G_ * B_;

        // prefetch epilogue xz (4 gates x float2) — hidden under MAC phase
        float2 xzv[4];
#pragma unroll
        for (int g = 0; g < 4; g++)
            xzv[g] = *reinterpret_cast<const float2*>(
                &xz_t[(size_t)(g * U_ + ub * 16 + eul) * B_ + bg0 + eb]);

        uint64_t acc[2][2];
        acc[0][0] = acc[0][1] = acc[1][0] = acc[1][1] = 0ull;

        // prefetch chunk 0 of h slice (128 k x 32 b)
        float4 pf[4];
#pragma unroll
        for (int i = 0; i < 4; i++) {
            int e = tid + i * 256;
            int kk = e >> 3, b4 = (e & 7) << 2;
            pf[i] = *reinterpret_cast<const float4*>(
                &hp[(size_t)kk * B_ + bg0 + b4]);
        }

        for (int kc = 0; kc < 4; kc++) {
            float* bc = buf + (kc & 1) * (128 * 32);
#pragma unroll
            for (int i = 0; i < 4; i++) {
                int e = tid + i * 256;
                int kk = e >> 3, b4 = (e & 7) << 2;
                *reinterpret_cast<float4*>(&bc[kk * 32 + b4]) = pf[i];
            }
            __syncthreads();
            if (kc < 3) {
                const float* hq = hp + (size_t)(kc + 1) * 128 * B_;
#pragma unroll
                for (int i = 0; i < 4; i++) {
                    int e = tid + i * 256;
                    int kk = e >> 3, b4 = (e & 7) << 2;
                    pf[i] = *reinterpret_cast<const float4*>(
                        &hq[(size_t)kk * B_ + bg0 + b4]);
                }
            }
            const float* wb = Ws + kc * 128 * 64;
#pragma unroll 32
            for (int kk = 0; kk < 128; kk++) {
                ulonglong2 h = *reinterpret_cast<ulonglong2*>(&bc[kk * 32 + b0]);
                float2 w = *reinterpret_cast<const float2*>(&wb[kk * 64 + c0]);
                uint64_t w0 = splat2(w.x), w1 = splat2(w.y);
                ffma2(acc[0][0], h.x, w0);
                ffma2(acc[1][0], h.y, w0);
                ffma2(acc[0][1], h.x, w1);
                ffma2(acc[1][1], h.y, w1);
            }
        }

        // stash z into stage0 (disjoint from stage1 still being read): [c][32]
        float* stash = buf;
#pragma unroll
        for (int c = 0; c < 2; c++) {
            float2 v0 = unpack2(acc[0][c]);
            float2 v1 = unpack2(acc[1][c]);
            *reinterpret_cast<float2*>(&stash[(c0 + c) * 32 + b0])     = v0;
            *reinterpret_cast<float2*>(&stash[(c0 + c) * 32 + b0 + 2]) = v1;
        }
        __syncthreads();

        // gate epilogue: 2 outputs per thread (float2 over batch)
        float* h_out = g_hseq + (size_t)t * U_ * B_;
        float2 z[4];
#pragma unroll
        for (int g = 0; g < 4; g++) {
            z[g].x = stash[(g * 16 + eul) * 32 + eb]     + xzv[g].x;
            z[g].y = stash[(g * 16 + eul) * 32 + eb + 1] + xzv[g].y;
        }
        float2 cold = *reinterpret_cast<float2*>(&cs[eul * 32 + eb]);
        float2 cnew, hnew;
        {
            float ig = 1.f / (1.f + __expf(-z[0].x));
            float fg = 1.f / (1.f + __expf(-z[1].x));
            float gg = 1.f - 2.f / (1.f + __expf(2.f * z[2].x));
            float og = 1.f / (1.f + __expf(-z[3].x));
            cnew.x = fg * cold.x + ig * gg;
            hnew.x = og * (1.f - 2.f / (1.f + __expf(2.f * cnew.x)));
        }
        {
            float ig = 1.f / (1.f + __expf(-z[0].y));
            float fg = 1.f / (1.f + __expf(-z[1].y));
            float gg = 1.f - 2.f / (1.f + __expf(2.f * z[2].y));
            float og = 1.f / (1.f + __expf(-z[3].y));
            cnew.y = fg * cold.y + ig * gg;
            hnew.y = og * (1.f - 2.f / (1.f + __expf(2.f * cnew.y)));
        }
        *reinterpret_cast<float2*>(&cs[eul * 32 + eb]) = cnew;
        *reinterpret_cast<float2*>(
            &h_out[(size_t)(ub * 16 + eul) * B_ + bg0 + eb]) = hnew;

        // software grid barrier
        __threadfence();
        __syncthreads();
        if (tid == 0) {
            atomicAdd(&g_bar, 1u);
            unsigned tgt = (unsigned)(NBLK * (t + 1));
            while (*((volatile unsigned*)&g_bar) < tgt) { }
            __threadfence();
        }
        __syncthreads();
    }
}

// ---------------------------------------------------------------------------
__global__ __launch_bounds__(256)
void softmax_kernel(float* __restrict__ out)
{
    __shared__ float red[256];
    const int row = blockIdx.x;
    const int tid = threadIdx.x;
    float* p = out + (size_t)row * CODES_;

    float v[4];
    float m = -1e30f;
#pragma unroll
    for (int i = 0; i < 4; i++) {
        v[i] = p[tid + i * 256];
        m = fmaxf(m, v[i]);
    }
    red[tid] = m;
    __syncthreads();
    for (int s = 128; s > 0; s >>= 1) {
        if (tid < s) red[tid] = fmaxf(red[tid], red[tid + s]);
        __syncthreads();
    }
    m = red[0];
    __syncthreads();

    float sum = 0.f;
#pragma unroll
    for (int i = 0; i < 4; i++) {
        v[i] = __expf(v[i] - m);
        sum += v[i];
    }
    red[tid] = sum;
    __syncthreads();
    for (int s = 128; s > 0; s >>= 1) {
        if (tid < s) red[tid] += red[tid + s];
        __syncthreads();
    }
    float inv = 1.f / red[0];
#pragma unroll
    for (int i = 0; i < 4; i++) p[tid + i * 256] = v[i] * inv;
}

// ---------------------------------------------------------------------------
extern "C" void kernel_launch(void* const* d_in, const int* in_sizes, int n_in,
                              void* d_out, int out_size)
{
    const float* x       = (const float*)d_in[0];
    const float* mask    = (const float*)d_in[1];
    const float* W_in    = (const float*)d_in[2];
    const float* W_rec   = (const float*)d_in[3];
    const float* b_lstm  = (const float*)d_in[4];
    const float* W_dense = (const float*)d_in[5];
    const float* b_dense = (const float*)d_in[6];
    float* out = (float*)d_out;

    const int smem_xz    = 2 * XZ_STAGE * 4;
    const int smem_dense = 2 * DN_STAGE * 4;
    const int smem_lstm  = (512 * 64 + 2 * 128 * 32 + 16 * 32) * (int)sizeof(float);
    static int attr_set = 0;
    if (!attr_set) {
        cudaFuncSetAttribute(gemm_xz_tc,
                             cudaFuncAttributeMaxDynamicSharedMemorySize, smem_xz);
        cudaFuncSetAttribute(gemm_dense_tc,
                             cudaFuncAttributeMaxDynamicSharedMemorySize, smem_dense);
        cudaFuncSetAttribute(lstm_persistent_kernel,
                             cudaFuncAttributeMaxDynamicSharedMemorySize, smem_lstm);
        attr_set = 1;
    }

    init_kernel<<<(U_ * B_ + 255) / 256, 256>>>();

    {   // xz = x @ W_in + b  (TC 3xTF32, double-buffered, transposed output)
        dim3 grid(G_ / 128, T_);
        gemm_xz_tc<<<grid, 512, smem_xz>>>(x, W_in, b_lstm);
    }

    lstm_persistent_kernel<<<NBLK, 256, smem_lstm>>>(W_rec);

    {   // dense + mask + relu (TC 3xTF32, double-buffered)
        dim3 grid(CODES_ / 128, T_);
        gemm_dense_tc<<<grid, 512, smem_dense>>>(W_dense, b_dense, mask, out);
    }

    softmax_kernel<<<T_ * B_, 256>>>(out);
}